// round 12
// baseline (speedup 1.0000x reference)
#include <cuda_runtime.h>
#include <cuda_bf16.h>

#define R_CONST   1.1f
#define SCALE_C   100.0f
#define S_STEPS   32
#define T_THETA   32
#define KDIM      128
#define NPB       128

// shared layout (bytes). A row stride = 136 bf16 = 68 u32 (bank-conflict-free frags)
#define A_OFF    0          // A bf16 [128][136] = 34816 B; later snh f32 stride 33 (16896 B)
#define BH_OFF   34816      // vh bf16 [32][136] = 8704 B
#define BL_OFF   43520      // vl bf16 [32][136] = 8704 B
#define SB_OFF   52224      // int sbatch[128]
#define BM_OFF   52736      // unsigned bmask[4]
#define SMEM_BYTES 52752

typedef unsigned int u32;

__device__ __forceinline__ float htanh(float z) {
    float th; asm("tanh.approx.f32 %0, %1;" : "=f"(th) : "f"(z)); return th;
}
__device__ __forceinline__ void mma16816(
    float& d0, float& d1, float& d2, float& d3,
    u32 a0, u32 a1, u32 a2, u32 a3, u32 b0, u32 b1)
{
    asm("mma.sync.aligned.m16n8k16.row.col.f32.bf16.bf16.f32 "
        "{%0,%1,%2,%3},{%4,%5,%6,%7},{%8,%9},{%0,%1,%2,%3};"
        : "+f"(d0), "+f"(d1), "+f"(d2), "+f"(d3)
        : "r"(a0), "r"(a1), "r"(a2), "r"(a3), "r"(b0), "r"(b1));
}

// ---------------------------------------------------------------------------
__global__ void zero_kernel(float* __restrict__ out, int n) {
    int i = blockIdx.x * blockDim.x + threadIdx.x;
    if (i < n) out[i] = 0.0f;
}

// ---------------------------------------------------------------------------
__global__ __launch_bounds__(256) void ect_kernel(
    const float* __restrict__ x,
    const int*   __restrict__ batch32,
    const float* __restrict__ v,
    float*       __restrict__ out,
    int nnodes)
{
    extern __shared__ __align__(16) char smb[];
    __nv_bfloat16* Ab = (__nv_bfloat16*)(smb + A_OFF);
    __nv_bfloat16* Bh = (__nv_bfloat16*)(smb + BH_OFF);
    __nv_bfloat16* Bl = (__nv_bfloat16*)(smb + BL_OFF);
    int*      sbatch = (int*)(smb + SB_OFF);
    unsigned* bmask  = (unsigned*)(smb + BM_OFF);

    const int tid    = threadIdx.x;
    const int wid    = tid >> 5;
    const int lane   = tid & 31;
    const int n0     = blockIdx.x * NPB;
    const int nvalid = min(NPB, nnodes - n0);
    if (nvalid <= 0) return;

    // batch dtype sniff (sorted, <128): int64 high word at last 32-bit slot == 0
    const bool is64 = (batch32[nnodes - 1] == 0);

    // stage pass 1: xh -> A
    for (int i = tid; i < NPB * KDIM; i += 256) {
        const int row = i >> 7, col = i & 127;
        const float f = (row < nvalid) ? x[(size_t)(n0 + row) * KDIM + col] : 0.0f;
        Ab[row * 136 + col] = __float2bfloat16(f);
    }
    // v -> vh, vl
    for (int i = tid; i < T_THETA * KDIM; i += 256) {
        const int row = i >> 7, col = i & 127;
        const float f = v[i];
        const __nv_bfloat16 bh = __float2bfloat16(f);
        Bh[row * 136 + col] = bh;
        Bl[row * 136 + col] = __float2bfloat16(f - __bfloat162float(bh));
    }
    for (int i = tid; i < nvalid; i += 256) {
        sbatch[i] = is64 ? batch32[2 * (n0 + i)] : batch32[n0 + i];
    }
    __syncthreads();

    // segment-boundary ballot
    if (tid < 128) {
        const bool f = (tid < nvalid) && (tid > 0) && (sbatch[tid] != sbatch[tid - 1]);
        const unsigned m = __ballot_sync(0xffffffffu, f);
        if ((lane) == 0) bmask[tid >> 5] = m;
    }

    // ---------------- Phase A: HMMA mma.sync ----------------
    const int g  = lane >> 2;     // group row 0..7
    const int tq = lane & 3;      // thread-in-group
    const int r0 = wid * 16 + g;  // this thread's first M row

    const u32* As  = (const u32*)(smb + A_OFF);
    const u32* Bhs = (const u32*)(smb + BH_OFF);
    const u32* Bls = (const u32*)(smb + BL_OFF);

    float d[4][4];
#pragma unroll
    for (int nt = 0; nt < 4; nt++)
#pragma unroll
        for (int j = 0; j < 4; j++) d[nt][j] = 0.0f;

    // pass 1: xh*vh + xh*vl
#pragma unroll
    for (int ks = 0; ks < 8; ks++) {
        const int kb = ks * 8;
        const u32 a0 = As[(r0)     * 68 + kb + tq];
        const u32 a1 = As[(r0 + 8) * 68 + kb + tq];
        const u32 a2 = As[(r0)     * 68 + kb + tq + 4];
        const u32 a3 = As[(r0 + 8) * 68 + kb + tq + 4];
#pragma unroll
        for (int nt = 0; nt < 4; nt++) {
            const int nr = nt * 8 + g;
            const u32 bh0 = Bhs[nr * 68 + kb + tq];
            const u32 bh1 = Bhs[nr * 68 + kb + tq + 4];
            mma16816(d[nt][0], d[nt][1], d[nt][2], d[nt][3], a0, a1, a2, a3, bh0, bh1);
            const u32 bl0 = Bls[nr * 68 + kb + tq];
            const u32 bl1 = Bls[nr * 68 + kb + tq + 4];
            mma16816(d[nt][0], d[nt][1], d[nt][2], d[nt][3], a0, a1, a2, a3, bl0, bl1);
        }
    }
    __syncthreads();   // all warps done reading A(xh)

    // stage pass 2: xl -> A (x reload hits L2)
    for (int i = tid; i < NPB * KDIM; i += 256) {
        const int row = i >> 7, col = i & 127;
        const float f = (row < nvalid) ? x[(size_t)(n0 + row) * KDIM + col] : 0.0f;
        const __nv_bfloat16 hi = __float2bfloat16(f);
        Ab[row * 136 + col] = __float2bfloat16(f - __bfloat162float(hi));
    }
    __syncthreads();

    // pass 2: xl*vh
#pragma unroll
    for (int ks = 0; ks < 8; ks++) {
        const int kb = ks * 8;
        const u32 a0 = As[(r0)     * 68 + kb + tq];
        const u32 a1 = As[(r0 + 8) * 68 + kb + tq];
        const u32 a2 = As[(r0)     * 68 + kb + tq + 4];
        const u32 a3 = As[(r0 + 8) * 68 + kb + tq + 4];
#pragma unroll
        for (int nt = 0; nt < 4; nt++) {
            const int nr = nt * 8 + g;
            const u32 bh0 = Bhs[nr * 68 + kb + tq];
            const u32 bh1 = Bhs[nr * 68 + kb + tq + 4];
            mma16816(d[nt][0], d[nt][1], d[nt][2], d[nt][3], a0, a1, a2, a3, bh0, bh1);
        }
    }
    __syncthreads();   // all warps done reading A(xl) -> overlay snh

    // write snh = 50*nh over dead A tile (f32, stride 33)
    float* snh = (float*)(smb + A_OFF);
#pragma unroll
    for (int nt = 0; nt < 4; nt++) {
        const int c = nt * 8 + tq * 2;
        snh[(r0)     * 33 + c]     = 50.0f * d[nt][0];
        snh[(r0)     * 33 + c + 1] = 50.0f * d[nt][1];
        snh[(r0 + 8) * 33 + c]     = 50.0f * d[nt][2];
        snh[(r0 + 8) * 33 + c + 1] = 50.0f * d[nt][3];
    }
    __syncthreads();

    // ---------------- Phase B (R3 verbatim) ----------------
    const int t  = lane;         // theta
    const int sg = wid;          // s-group (4 s values)

    float c50[4], kterm[4];
#pragma unroll
    for (int i = 0; i < 4; i++) {
        const int s = sg * 4 + i;
        const float lin = -R_CONST + (float)s * (2.0f * R_CONST / 31.0f);
        c50[i]   = 50.0f * lin;
        kterm[i] = 0.5f - 1.0f / (1.0f + __expf(SCALE_C * (R_CONST - lin)));
    }

    const unsigned bm0 = bmask[0], bm1 = bmask[1], bm2 = bmask[2], bm3 = bmask[3];

    int n   = 0;
    int cur = sbatch[0];
    while (n < nvalid) {
        // next boundary strictly > n (block-uniform)
        int ne = nvalid;
        {
            int p = n + 1;
            int w = p >> 5;
            unsigned m = 0;
            if (w < 4) {
                const unsigned wv = (w == 0) ? bm0 : (w == 1) ? bm1 : (w == 2) ? bm2 : bm3;
                m = wv & (0xFFFFFFFFu << (p & 31));
            }
            while (w < 4) {
                if (m) { ne = min(nvalid, (w << 5) + __ffs(m) - 1); break; }
                w++;
                if (w < 4) m = (w == 1) ? bm1 : (w == 2) ? bm2 : bm3;
            }
        }

        float a2[4] = {0.f, 0.f, 0.f, 0.f};
#pragma unroll 4
        for (int m2 = n; m2 < ne; m2++) {
            const float h = snh[m2 * 33 + t];
#pragma unroll
            for (int i = 0; i < 4; i++) {
                const float z = c50[i] - h;
                a2[i] = fmaf(0.5f, htanh(z), a2[i]);
            }
        }
        const float fc = (float)(ne - n);
#pragma unroll
        for (int i = 0; i < 4; i++) {
            atomicAdd(&out[(cur * S_STEPS + (sg * 4 + i)) * T_THETA + t],
                      fmaf(fc, kterm[i], a2[i]));
        }
        n = ne;
        if (n < nvalid) cur = sbatch[n];
    }
}

// ---------------------------------------------------------------------------
extern "C" void kernel_launch(void* const* d_in, const int* in_sizes, int n_in,
                              void* d_out, int out_size)
{
    const float* x = nullptr;
    const int*   batch = nullptr;
    const float* v = nullptr;
    int nnodes = 0;

    for (int i = 0; i < n_in; i++) {
        const int sz = in_sizes[i];
        if (sz > 1000000) {
            x = (const float*)d_in[i];
        } else if (sz == T_THETA * KDIM) {
            v = (const float*)d_in[i];
        } else if (sz > 1) {
            batch = (const int*)d_in[i];
            nnodes = sz;
        }
    }
    float* out = (float*)d_out;

    cudaFuncSetAttribute(ect_kernel,
                         cudaFuncAttributeMaxDynamicSharedMemorySize, SMEM_BYTES);

    zero_kernel<<<(out_size + 255) / 256, 256>>>(out, out_size);

    const int blocks = (nnodes + NPB - 1) / NPB;
    ect_kernel<<<blocks, 256, SMEM_BYTES>>>(x, batch, v, out, nnodes);
}